// round 5
// baseline (speedup 1.0000x reference)
#include <cuda_runtime.h>
#include <math.h>

#define HH 512
#define WW 1024
#define BATCH 4
#define BW 32
#define BH 8

// ---------------- double-word (compensated fp32) arithmetic ----------------
struct dd { float hi, lo; };

__device__ __forceinline__ dd dd_renorm(float s, float e) {
    float t = __fadd_rn(s, e);
    dd r; r.hi = t; r.lo = __fsub_rn(e, __fsub_rn(t, s));
    return r;
}
__device__ __forceinline__ dd dd_zero() { dd r; r.hi = 0.f; r.lo = 0.f; return r; }

// acc += x*y  (TwoProd + TwoSum, fully compensated)
__device__ __forceinline__ dd dd_add_prod(dd a, float x, float y) {
    float p = __fmul_rn(x, y);
    float e = fmaf(x, y, -p);
    float s  = __fadd_rn(a.hi, p);
    float bb = __fsub_rn(s, a.hi);
    float err = __fadd_rn(__fsub_rn(a.hi, __fsub_rn(s, bb)),
                          __fsub_rn(p, bb));
    err = __fadd_rn(err, __fadd_rn(a.lo, e));
    return dd_renorm(s, err);
}
// acc += f
__device__ __forceinline__ dd dd_add_f(dd a, float p) {
    float s  = __fadd_rn(a.hi, p);
    float bb = __fsub_rn(s, a.hi);
    float err = __fadd_rn(__fsub_rn(a.hi, __fsub_rn(s, bb)),
                          __fsub_rn(p, bb));
    err = __fadd_rn(err, a.lo);
    return dd_renorm(s, err);
}
__device__ __forceinline__ dd dd_add(dd a, dd b) {
    float s  = __fadd_rn(a.hi, b.hi);
    float bb = __fsub_rn(s, a.hi);
    float err = __fadd_rn(__fsub_rn(a.hi, __fsub_rn(s, bb)),
                          __fsub_rn(b.hi, bb));
    err = __fadd_rn(err, __fadd_rn(a.lo, b.lo));
    return dd_renorm(s, err);
}
__device__ __forceinline__ dd dd_neg(dd a) { dd r; r.hi = -a.hi; r.lo = -a.lo; return r; }
__device__ __forceinline__ dd dd_sub(dd a, dd b) { return dd_add(a, dd_neg(b)); }
__device__ __forceinline__ dd dd_mul(dd a, dd b) {
    float p = __fmul_rn(a.hi, b.hi);
    float e = fmaf(a.hi, b.hi, -p);
    e = fmaf(a.hi, b.lo, e);
    e = fmaf(a.lo, b.hi, e);
    return dd_renorm(p, e);
}
// a*bx + b*by + c*bz  (all dd)
__device__ __forceinline__ dd dd_dot3(dd a, dd bx, dd b, dd by, dd c, dd bz) {
    return dd_add(dd_add(dd_mul(a, bx), dd_mul(b, by)), dd_mul(c, bz));
}

// ---------------- ray tables ----------------
// theta/phi computed in the reference's exact fp32 chain; sin/cos evaluated in
// DOUBLE and rounded to fp32 -> correctly-rounded float results.
__device__ float g_st[WW];
__device__ float g_ct[WW];
__device__ float g_sp[HH];
__device__ float g_cp[HH];

__global__ void rays_kernel() {
    int t = blockIdx.x * blockDim.x + threadIdx.x;
    const float PI_F = 3.14159265358979323846f;   // fl32(pi)
    if (t < WW) {
        float jn = __fmul_rn((float)t + 0.5f, 1.0f / (float)WW);
        float th = __fsub_rn(__fmul_rn(jn, __fmul_rn(2.0f, PI_F)), PI_F);
        double thd = (double)th;
        g_st[t] = (float)sin(thd);
        g_ct[t] = (float)cos(thd);
    } else if (t < WW + HH) {
        int i = t - WW;
        float in_ = __fmul_rn((float)i + 0.5f, 1.0f / (float)HH);
        float ph = __fsub_rn(0.5f * PI_F, __fmul_rn(in_, PI_F));
        double phd = (double)ph;
        g_sp[i] = (float)sin(phd);
        g_cp[i] = (float)cos(phd);
    }
}

__global__ __launch_bounds__(BW * BH)
void normals_kernel(const float* __restrict__ depth, float* __restrict__ out) {
    __shared__ float4 pts[BH + 2][BW + 2];

    const int bb = blockIdx.z;
    const int i0 = blockIdx.y * BH;
    const int j0 = blockIdx.x * BW;
    const int tid = threadIdx.y * BW + threadIdx.x;
    const float* dptr = depth + (size_t)bb * (HH * WW);

    // (BH+2)x(BW+2) tile of fp32 3D points (the reference's data tensor),
    // zero-padded outside the image.
    for (int t = tid; t < (BH + 2) * (BW + 2); t += BW * BH) {
        int ly = t / (BW + 2);
        int lx = t - ly * (BW + 2);
        int gi = i0 + ly - 1;
        int gj = j0 + lx - 1;
        float4 p = make_float4(0.0f, 0.0f, 0.0f, 0.0f);
        if (gi >= 0 && gi < HH && gj >= 0 && gj < WW) {
            float d  = __ldg(&dptr[(size_t)gi * WW + gj]);
            float st = g_st[gj];
            float ct = g_ct[gj];
            float sp = g_sp[gi];
            float cp = g_cp[gi];
            float x = __fmul_rn(cp, st);
            float z = __fmul_rn(cp, ct);
            p.x = __fmul_rn(d, x);
            p.y = __fmul_rn(d, sp);
            p.z = __fmul_rn(d, z);
        }
        pts[ly][lx] = p;
    }
    __syncthreads();

    // G and b accumulated EXACTLY (double-word): my result becomes the true
    // mathematical normal for the fp32 points tensor; all remaining rel_err
    // is the reference's own fp32 rounding noise.
    dd ga = dd_zero(), gb = dd_zero(), gc = dd_zero();
    dd gd = dd_zero(), ge = dd_zero(), gf = dd_zero();
    dd bx = dd_zero(), by = dd_zero(), bz = dd_zero();
#pragma unroll
    for (int di = 0; di < 3; di++) {
#pragma unroll
        for (int dj = 0; dj < 3; dj++) {
            float4 p = pts[threadIdx.y + di][threadIdx.x + dj];
            ga = dd_add_prod(ga, p.x, p.x);
            gb = dd_add_prod(gb, p.x, p.y);
            gc = dd_add_prod(gc, p.x, p.z);
            gd = dd_add_prod(gd, p.y, p.y);
            ge = dd_add_prod(ge, p.y, p.z);
            gf = dd_add_prod(gf, p.z, p.z);
            bx = dd_add_f(bx, p.x);
            by = dd_add_f(by, p.y);
            bz = dd_add_f(bz, p.z);
        }
    }
    ga = dd_add_f(ga, 1e-5f);
    gd = dd_add_f(gd, 1e-5f);
    gf = dd_add_f(gf, 1e-5f);

    // Symmetric adjugate in double-word precision. det(G) > 0 (SPD + eps), and
    // the final normalization removes the positive det factor, so m = adj(G)*b
    // has the exact direction of G^{-1} b.
    dd A00 = dd_sub(dd_mul(gd, gf), dd_mul(ge, ge));
    dd A01 = dd_sub(dd_mul(gc, ge), dd_mul(gb, gf));
    dd A02 = dd_sub(dd_mul(gb, ge), dd_mul(gc, gd));
    dd A11 = dd_sub(dd_mul(ga, gf), dd_mul(gc, gc));
    dd A12 = dd_sub(dd_mul(gb, gc), dd_mul(ga, ge));
    dd A22 = dd_sub(dd_mul(ga, gd), dd_mul(gb, gb));

    dd md0 = dd_dot3(A00, bx, A01, by, A02, bz);
    dd md1 = dd_dot3(A01, bx, A11, by, A12, bz);
    dd md2 = dd_dot3(A02, bx, A12, by, A22, bz);

    float m0 = md0.hi;   // hi = correctly-rounded fp32 of the dd value
    float m1 = md1.hi;
    float m2 = md2.hi;

    // fp32 normalize (reference semantics; noise here is ~ulp, negligible)
    float nn = __fmul_rn(m0, m0);
    nn = __fadd_rn(nn, __fmul_rn(m1, m1));
    nn = __fadd_rn(nn, __fmul_rn(m2, m2));
    float norm = sqrtf(nn);
    if (norm == 0.0f) norm = 1e-4f;
    float o0 = __fdiv_rn(-m0, norm);
    float o1 = __fdiv_rn(-m1, norm);
    float o2 = __fdiv_rn(-m2, norm);

    const int gi = i0 + threadIdx.y;
    const int gj = j0 + threadIdx.x;
    size_t base = (size_t)bb * 3 * (HH * WW) + (size_t)gi * WW + gj;
    out[base]               = o0;
    out[base +     HH * WW] = o1;
    out[base + 2 * HH * WW] = o2;
}

extern "C" void kernel_launch(void* const* d_in, const int* in_sizes, int n_in,
                              void* d_out, int out_size) {
    const float* depth = (const float*)d_in[0];
    float* out = (float*)d_out;

    rays_kernel<<<(WW + HH + 255) / 256, 256>>>();

    dim3 block(BW, BH, 1);
    dim3 grid(WW / BW, HH / BH, BATCH);
    normals_kernel<<<grid, block>>>(depth, out);
}

// round 6
// speedup vs baseline: 1.5815x; 1.5815x over previous
#include <cuda_runtime.h>
#include <math.h>

#define HH 512
#define WW 1024
#define BATCH 4
#define BW 32
#define BH 8

// ---------------- exact helpers (TwoProd / TwoSum based, renorm-free) ------
// All pair values (s, lo) satisfy s + lo == exact sum to ~2^-45 relative.

// sum of 3 products a_i*b_i, exact: hi via TwoSum chain, all error terms in lo
__device__ __forceinline__ float2 sum3prod(float a0, float b0,
                                           float a1, float b1,
                                           float a2, float b2) {
    float p0 = __fmul_rn(a0, b0), e0 = fmaf(a0, b0, -p0);
    float p1 = __fmul_rn(a1, b1), e1 = fmaf(a1, b1, -p1);
    float p2 = __fmul_rn(a2, b2), e2 = fmaf(a2, b2, -p2);
    float s  = __fadd_rn(p0, p1);
    float bb = __fsub_rn(s, p0);
    float er1 = __fadd_rn(__fsub_rn(p0, __fsub_rn(s, bb)), __fsub_rn(p1, bb));
    float s2  = __fadd_rn(s, p2);
    float bb2 = __fsub_rn(s2, s);
    float er2 = __fadd_rn(__fsub_rn(s, __fsub_rn(s2, bb2)), __fsub_rn(p2, bb2));
    float lo = __fadd_rn(__fadd_rn(__fadd_rn(e0, e1), e2), __fadd_rn(er1, er2));
    return make_float2(s2, lo);
}

// exact sum of 3 plain floats
__device__ __forceinline__ float2 sum3(float p0, float p1, float p2) {
    float s  = __fadd_rn(p0, p1);
    float bb = __fsub_rn(s, p0);
    float er1 = __fadd_rn(__fsub_rn(p0, __fsub_rn(s, bb)), __fsub_rn(p1, bb));
    float s2  = __fadd_rn(s, p2);
    float bb2 = __fsub_rn(s2, s);
    float er2 = __fadd_rn(__fsub_rn(s, __fsub_rn(s2, bb2)), __fsub_rn(p2, bb2));
    return make_float2(s2, __fadd_rn(er1, er2));
}

// exact sum of 3 dd pairs (hi TwoSum chain, lo accumulated plainly)
__device__ __forceinline__ float2 sum3dd(float2 a, float2 b, float2 c) {
    float s  = __fadd_rn(a.x, b.x);
    float bb = __fsub_rn(s, a.x);
    float er1 = __fadd_rn(__fsub_rn(a.x, __fsub_rn(s, bb)), __fsub_rn(b.x, bb));
    float s2  = __fadd_rn(s, c.x);
    float bb2 = __fsub_rn(s2, s);
    float er2 = __fadd_rn(__fsub_rn(s, __fsub_rn(s2, bb2)), __fsub_rn(c.x, bb2));
    float lo = __fadd_rn(__fadd_rn(__fadd_rn(a.y, b.y), c.y), __fadd_rn(er1, er2));
    return make_float2(s2, lo);
}

// dd += plain float, exact
__device__ __forceinline__ float2 ddaddf(float2 a, float p) {
    float s  = __fadd_rn(a.x, p);
    float bb = __fsub_rn(s, a.x);
    float er = __fadd_rn(__fsub_rn(a.x, __fsub_rn(s, bb)), __fsub_rn(p, bb));
    return make_float2(s, __fadd_rn(a.y, er));
}

// relaxed dd multiply: (p, e) with p+e ~= a*b (drops lo*lo term)
__device__ __forceinline__ float2 ddmul(float2 a, float2 b) {
    float p = __fmul_rn(a.x, b.x);
    float e = fmaf(a.x, b.x, -p);
    e = fmaf(a.x, b.y, e);
    e = fmaf(a.y, b.x, e);
    return make_float2(p, e);
}

// cofactor a*b - c*d (all dd), exact hi-difference via TwoSum
__device__ __forceinline__ float2 ddcof(float2 a, float2 b, float2 c, float2 d) {
    float2 p = ddmul(a, b);
    float2 q = ddmul(c, d);
    float s  = __fsub_rn(p.x, q.x);
    float bb = __fsub_rn(s, p.x);
    float er = __fadd_rn(__fsub_rn(p.x, __fsub_rn(s, bb)), __fsub_rn(-q.x, bb));
    return make_float2(s, __fadd_rn(er, __fsub_rn(p.y, q.y)));
}

// ---------------- ray tables (sin/cos in double, rounded to fp32) ----------
__device__ float g_st[WW];
__device__ float g_ct[WW];
__device__ float g_sp[HH];
__device__ float g_cp[HH];

__global__ void rays_kernel() {
    int t = blockIdx.x * blockDim.x + threadIdx.x;
    const float PI_F = 3.14159265358979323846f;   // fl32(pi)
    if (t < WW) {
        float jn = __fmul_rn((float)t + 0.5f, 1.0f / (float)WW);
        float th = __fsub_rn(__fmul_rn(jn, __fmul_rn(2.0f, PI_F)), PI_F);
        double thd = (double)th;
        g_st[t] = (float)sin(thd);
        g_ct[t] = (float)cos(thd);
    } else if (t < WW + HH) {
        int i = t - WW;
        float in_ = __fmul_rn((float)i + 0.5f, 1.0f / (float)HH);
        float ph = __fsub_rn(0.5f * PI_F, __fmul_rn(in_, PI_F));
        double phd = (double)ph;
        g_sp[i] = (float)sin(phd);
        g_cp[i] = (float)cos(phd);
    }
}

// quantity order: 0:xx 1:xy 2:xz 3:yy 4:yz 5:zz 6:x 7:y 8:z
__global__ __launch_bounds__(BW * BH)
void normals_kernel(const float* __restrict__ depth, float* __restrict__ out) {
    __shared__ float4 pts[BH + 2][BW + 2];
    __shared__ float2 Hs[9][BH + 2][BW];

    const int bb = blockIdx.z;
    const int i0 = blockIdx.y * BH;
    const int j0 = blockIdx.x * BW;
    const int tid = threadIdx.y * BW + threadIdx.x;
    const float* dptr = depth + (size_t)bb * (HH * WW);

    // Phase A: (BH+2)x(BW+2) tile of fp32 3D points, zero-padded.
    for (int t = tid; t < (BH + 2) * (BW + 2); t += BW * BH) {
        int ly = t / (BW + 2);
        int lx = t - ly * (BW + 2);
        int gi = i0 + ly - 1;
        int gj = j0 + lx - 1;
        float4 p = make_float4(0.0f, 0.0f, 0.0f, 0.0f);
        if (gi >= 0 && gi < HH && gj >= 0 && gj < WW) {
            float d  = __ldg(&dptr[(size_t)gi * WW + gj]);
            float st = g_st[gj];
            float ct = g_ct[gj];
            float sp = g_sp[gi];
            float cp = g_cp[gi];
            float x = __fmul_rn(cp, st);
            float z = __fmul_rn(cp, ct);
            p.x = __fmul_rn(d, x);
            p.y = __fmul_rn(d, sp);
            p.z = __fmul_rn(d, z);
        }
        pts[ly][lx] = p;
    }
    __syncthreads();

    // Phase B: exact horizontal 3-window sums of the 9 quantities, for all
    // (BH+2) rows x BW center columns. Shared across 3 output rows each.
    for (int t = tid; t < (BH + 2) * BW; t += BW * BH) {
        int ly = t / BW;
        int lx = t - ly * BW;           // center column = lx+1 in padded coords
        float4 p0 = pts[ly][lx];
        float4 p1 = pts[ly][lx + 1];
        float4 p2 = pts[ly][lx + 2];
        Hs[0][ly][lx] = sum3prod(p0.x, p0.x, p1.x, p1.x, p2.x, p2.x);
        Hs[1][ly][lx] = sum3prod(p0.x, p0.y, p1.x, p1.y, p2.x, p2.y);
        Hs[2][ly][lx] = sum3prod(p0.x, p0.z, p1.x, p1.z, p2.x, p2.z);
        Hs[3][ly][lx] = sum3prod(p0.y, p0.y, p1.y, p1.y, p2.y, p2.y);
        Hs[4][ly][lx] = sum3prod(p0.y, p0.z, p1.y, p1.z, p2.y, p2.z);
        Hs[5][ly][lx] = sum3prod(p0.z, p0.z, p1.z, p1.z, p2.z, p2.z);
        Hs[6][ly][lx] = sum3(p0.x, p1.x, p2.x);
        Hs[7][ly][lx] = sum3(p0.y, p1.y, p2.y);
        Hs[8][ly][lx] = sum3(p0.z, p1.z, p2.z);
    }
    __syncthreads();

    // Phase C: exact vertical 3-sums -> dd G and b; dd adjugate solve.
    const int ty = threadIdx.y;
    const int tx = threadIdx.x;
    float2 ga = sum3dd(Hs[0][ty][tx], Hs[0][ty + 1][tx], Hs[0][ty + 2][tx]);
    float2 gb = sum3dd(Hs[1][ty][tx], Hs[1][ty + 1][tx], Hs[1][ty + 2][tx]);
    float2 gc = sum3dd(Hs[2][ty][tx], Hs[2][ty + 1][tx], Hs[2][ty + 2][tx]);
    float2 gd = sum3dd(Hs[3][ty][tx], Hs[3][ty + 1][tx], Hs[3][ty + 2][tx]);
    float2 ge = sum3dd(Hs[4][ty][tx], Hs[4][ty + 1][tx], Hs[4][ty + 2][tx]);
    float2 gf = sum3dd(Hs[5][ty][tx], Hs[5][ty + 1][tx], Hs[5][ty + 2][tx]);
    float2 bx = sum3dd(Hs[6][ty][tx], Hs[6][ty + 1][tx], Hs[6][ty + 2][tx]);
    float2 by = sum3dd(Hs[7][ty][tx], Hs[7][ty + 1][tx], Hs[7][ty + 2][tx]);
    float2 bz = sum3dd(Hs[8][ty][tx], Hs[8][ty + 1][tx], Hs[8][ty + 2][tx]);

    ga = ddaddf(ga, 1e-5f);
    gd = ddaddf(gd, 1e-5f);
    gf = ddaddf(gf, 1e-5f);

    // Symmetric adjugate (det > 0 for SPD+eps; direction preserved).
    float2 A00 = ddcof(gd, gf, ge, ge);
    float2 A01 = ddcof(gc, ge, gb, gf);
    float2 A02 = ddcof(gb, ge, gc, gd);
    float2 A11 = ddcof(ga, gf, gc, gc);
    float2 A12 = ddcof(gb, gc, ga, ge);
    float2 A22 = ddcof(ga, gd, gb, gb);

    // m = adj(G) * b in dd; collapse with one final add (cancellation-heavy,
    // so the hi chain must stay exact -> sum3dd).
    float2 md0 = sum3dd(ddmul(A00, bx), ddmul(A01, by), ddmul(A02, bz));
    float2 md1 = sum3dd(ddmul(A01, bx), ddmul(A11, by), ddmul(A12, bz));
    float2 md2 = sum3dd(ddmul(A02, bx), ddmul(A12, by), ddmul(A22, bz));

    float m0 = __fadd_rn(md0.x, md0.y);
    float m1 = __fadd_rn(md1.x, md1.y);
    float m2 = __fadd_rn(md2.x, md2.y);

    // fp32 normalize (reference semantics)
    float nn = __fmul_rn(m0, m0);
    nn = __fadd_rn(nn, __fmul_rn(m1, m1));
    nn = __fadd_rn(nn, __fmul_rn(m2, m2));
    float norm = sqrtf(nn);
    if (norm == 0.0f) norm = 1e-4f;
    float o0 = __fdiv_rn(-m0, norm);
    float o1 = __fdiv_rn(-m1, norm);
    float o2 = __fdiv_rn(-m2, norm);

    const int gi = i0 + ty;
    const int gj = j0 + tx;
    size_t base = (size_t)bb * 3 * (HH * WW) + (size_t)gi * WW + gj;
    out[base]               = o0;
    out[base +     HH * WW] = o1;
    out[base + 2 * HH * WW] = o2;
}

extern "C" void kernel_launch(void* const* d_in, const int* in_sizes, int n_in,
                              void* d_out, int out_size) {
    const float* depth = (const float*)d_in[0];
    float* out = (float*)d_out;

    rays_kernel<<<(WW + HH + 255) / 256, 256>>>();

    dim3 block(BW, BH, 1);
    dim3 grid(WW / BW, HH / BH, BATCH);
    normals_kernel<<<grid, block>>>(depth, out);
}